// round 3
// baseline (speedup 1.0000x reference)
#include <cuda_runtime.h>
#include <math.h>

#define B_    256
#define V_    128000
#define H_    200
#define TOPK  50
#define TOPSZ 64               // sorted slots kept (>= 50 + tie slack)

constexpr float TOPP = 0.9f;
constexpr float TEMP = 0.6f;
constexpr float PEN  = 1.2f;

#define NT     512
#define NBINS  2048            // top 11 bits of ordered-uint
#define BSHIFT 21              // 32 - 11
#define BPC    (NBINS / NT)    // 4 bins per thread
#define CAP    2048
#define MASKW  (V_ / 32)       // 4000 words
#define IDXMASK 0x1FFFF        // vocab idx fits in 17 bits (V < 131072)

__device__ __forceinline__ unsigned ordu(float f) {
    unsigned u = __float_as_uint(f);
    return (u & 0x80000000u) ? ~u : (u | 0x80000000u);
}

__global__ __launch_bounds__(NT) void sample_kernel(
    const float* __restrict__ logits,
    const int*   __restrict__ prev,
    float*       __restrict__ out)
{
    __shared__ unsigned sm_mask[MASKW];   // 16000 B
    __shared__ int      sm_hist[NBINS];   //  8192 B
    __shared__ float    sm_cval[CAP];     //  8192 B
    __shared__ int      sm_cidx[CAP];     //  8192 B (idx | rank<<17 after ranking)
    __shared__ int      sm_chunk[NT];     //  2048 B
    __shared__ float    sm_top[TOPSZ];
    __shared__ float    sm_e[TOPSZ];
    __shared__ int      sm_cnt;
    __shared__ int      sm_bstar;
    __shared__ int      sm_m;
    __shared__ float    sm_v0, sm_invZ;

    const int row = blockIdx.x;
    const int tid = threadIdx.x;

    const float4* __restrict__ l4 = (const float4*)(logits + (size_t)row * V_);
    float4* o4 = (float4*)(out + (size_t)row * V_);
    float*  orow = out + (size_t)row * V_;
    const int NV4 = V_ / 4;

    // ---- init shared state ----
    for (int i = tid; i < MASKW; i += NT) sm_mask[i] = 0u;
    for (int i = tid; i < NBINS; i += NT) sm_hist[i] = 0;
    if (tid == 0) sm_cnt = 0;
    __syncthreads();
    for (int i = tid; i < H_; i += NT) {
        int t = prev[row * H_ + i];
        atomicOr(&sm_mask[((unsigned)t) >> 5], 1u << (t & 31));
    }
    __syncthreads();

    // ---- Pass 1: histogram of adjusted logits + zero-fill output row ----
    for (int i = tid; i < NV4; i += NT) {
        float4 v = l4[i];
        int j = i << 2;
        unsigned mw = sm_mask[j >> 5];
        unsigned sh = j & 31;
        float a;
        a = v.x; if ((mw >> (sh + 0)) & 1u) a = (a < 0.f) ? a * PEN : a / PEN; a /= TEMP;
        atomicAdd(&sm_hist[ordu(a) >> BSHIFT], 1);
        a = v.y; if ((mw >> (sh + 1)) & 1u) a = (a < 0.f) ? a * PEN : a / PEN; a /= TEMP;
        atomicAdd(&sm_hist[ordu(a) >> BSHIFT], 1);
        a = v.z; if ((mw >> (sh + 2)) & 1u) a = (a < 0.f) ? a * PEN : a / PEN; a /= TEMP;
        atomicAdd(&sm_hist[ordu(a) >> BSHIFT], 1);
        a = v.w; if ((mw >> (sh + 3)) & 1u) a = (a < 0.f) ? a * PEN : a / PEN; a /= TEMP;
        atomicAdd(&sm_hist[ordu(a) >> BSHIFT], 1);
        o4[i] = make_float4(0.f, 0.f, 0.f, 0.f);
    }
    __syncthreads();

    // ---- find the bin containing the 50th-largest value ----
    {
        int s = 0;
        #pragma unroll
        for (int k = 0; k < BPC; k++) s += sm_hist[tid * BPC + k];
        sm_chunk[tid] = s;
        __syncthreads();
        for (int off = 1; off < NT; off <<= 1) {   // inclusive suffix scan
            int add = (tid + off < NT) ? sm_chunk[tid + off] : 0;
            __syncthreads();
            sm_chunk[tid] += add;
            __syncthreads();
        }
        int myv = sm_chunk[tid];
        int nxt = (tid + 1 < NT) ? sm_chunk[tid + 1] : 0;
        if (myv >= TOPK && nxt < TOPK) {
            int run = nxt;
            int bstar = tid * BPC;
            for (int b = tid * BPC + BPC - 1; b >= tid * BPC; b--) {
                run += sm_hist[b];
                if (run >= TOPK) { bstar = b; break; }
            }
            sm_bstar = bstar;
        }
    }
    __syncthreads();
    const unsigned uth = ((unsigned)sm_bstar) << BSHIFT;

    // ---- Pass 2: collect candidates (all values in/above the rank-50 bin) ----
    for (int i = tid; i < NV4; i += NT) {
        float4 v = l4[i];
        int j = i << 2;
        unsigned mw = sm_mask[j >> 5];
        unsigned sh = j & 31;
        float a0 = v.x; if ((mw >> (sh + 0)) & 1u) a0 = (a0 < 0.f) ? a0 * PEN : a0 / PEN; a0 /= TEMP;
        float a1 = v.y; if ((mw >> (sh + 1)) & 1u) a1 = (a1 < 0.f) ? a1 * PEN : a1 / PEN; a1 /= TEMP;
        float a2 = v.z; if ((mw >> (sh + 2)) & 1u) a2 = (a2 < 0.f) ? a2 * PEN : a2 / PEN; a2 /= TEMP;
        float a3 = v.w; if ((mw >> (sh + 3)) & 1u) a3 = (a3 < 0.f) ? a3 * PEN : a3 / PEN; a3 /= TEMP;
        if (ordu(a0) >= uth) { int p = atomicAdd(&sm_cnt, 1); if (p < CAP) { sm_cval[p] = a0; sm_cidx[p] = j + 0; } }
        if (ordu(a1) >= uth) { int p = atomicAdd(&sm_cnt, 1); if (p < CAP) { sm_cval[p] = a1; sm_cidx[p] = j + 1; } }
        if (ordu(a2) >= uth) { int p = atomicAdd(&sm_cnt, 1); if (p < CAP) { sm_cval[p] = a2; sm_cidx[p] = j + 2; } }
        if (ordu(a3) >= uth) { int p = atomicAdd(&sm_cnt, 1); if (p < CAP) { sm_cval[p] = a3; sm_cidx[p] = j + 3; } }
    }
    __syncthreads();
    const int n = sm_cnt < CAP ? sm_cnt : CAP;

    // ---- counting-rank selection with VOCAB-INDEX tiebreak (stable, = argsort) ----
    // Packs each candidate's rank into bits [17..24] of its index word.
    // Concurrent packed writes are safe: readers mask to the low 17 bits, which
    // are identical before and after the (word-atomic) store.
    for (int i = tid; i < n; i += NT) {
        float v = sm_cval[i];
        int idx = sm_cidx[i] & IDXMASK;
        int r = 0;
        for (int k = 0; k < n; k++) {
            float w = sm_cval[k];
            r += (w > v) || (w == v && (sm_cidx[k] & IDXMASK) < idx);
        }
        if (r < TOPSZ) sm_top[r] = v;
        int rc = r < 255 ? r : 255;
        sm_cidx[i] = idx | (rc << 17);
    }
    __syncthreads();

    // ---- top-k tie extension + nucleus (top-p) cut, HF shift-right semantics ----
    if (tid == 0) {
        // JAX keeps ALL values equal to the 50th-largest (logits < kth -> -inf)
        float v50 = sm_top[TOPK - 1];
        int lim = n < TOPSZ ? n : TOPSZ;
        int nk = TOPK;
        while (nk < lim && sm_top[nk] == v50) nk++;

        float v0 = sm_top[0];
        float Z = 0.f;
        for (int i = 0; i < nk; i++) { sm_e[i] = expf(sm_top[i] - v0); Z += sm_e[i]; }
        float cum = 0.f, S = 0.f;
        int m = 0;
        for (int i = 0; i < nk; i++) {
            if (i > 0 && cum > TOPP) break;   // remove i iff cum_{i-1} > p
            cum += sm_e[i] / Z;               // mimic JAX: cumsum of normalized probs
            S   += sm_e[i];
            m = i + 1;
        }
        sm_v0   = v0;
        sm_m    = m;
        sm_invZ = 1.f / S;                    // S = sum of kept e's
    }
    __syncthreads();

    // ---- write kept probabilities by RANK (rest already zeroed) ----
    const float v0 = sm_v0, invZ = sm_invZ;
    const int m = sm_m;
    for (int i = tid; i < n; i += NT) {
        int packed = sm_cidx[i];
        int r = packed >> 17;
        if (r < m) orow[packed & IDXMASK] = expf(sm_cval[i] - v0) * invZ;
    }
}

extern "C" void kernel_launch(void* const* d_in, const int* in_sizes, int n_in,
                              void* d_out, int out_size) {
    const float* logits = (const float*)d_in[0];
    const int*   prev   = (const int*)d_in[1];
    float*       out    = (float*)d_out;
    sample_kernel<<<B_, NT>>>(logits, prev, out);
}

// round 4
// speedup vs baseline: 1.6661x; 1.6661x over previous
#include <cuda_runtime.h>
#include <math.h>

#define B_    256
#define V_    128000
#define H_    200
#define TOPK  50
#define TOPSZ 64

constexpr float TOPP = 0.9f;
constexpr float TEMP = 0.6f;
constexpr float PEN  = 1.2f;

// ---------- pass-1 streaming config ----------
#define SPLIT  8
#define TILE   (V_ / SPLIT)      // 16000 elements per block
#define TW     (TILE / 32)       // 500 mask words
#define NT     512
#define CAP    1024
constexpr float T0 = 4.8f;       // conservative static candidate threshold (adjusted units)

// ---------- fallback (exact two-pass) config ----------
#define NBINS   2048
#define BSHIFT  21
#define BPC     (NBINS / NT)
#define CAPF    2048
#define MASKW   (V_ / 32)
#define IDXMASK 0x1FFFF

// ---------- device scratch (static: no allocation) ----------
__device__ int   g_cnt[B_];
__device__ float g_cval[B_][CAP];
__device__ int   g_cidx[B_][CAP];

__device__ __forceinline__ unsigned ordu(float f) {
    unsigned u = __float_as_uint(f);
    return (u & 0x80000000u) ? ~u : (u | 0x80000000u);
}

// ============ K0: zero the per-row counters ============
__global__ void zero_kernel() {
    g_cnt[threadIdx.x] = 0;
}

// ============ K1: stream logits once: penalty+temp, zero-fill out, collect candidates ============
__global__ __launch_bounds__(NT) void pass1_kernel(
    const float* __restrict__ logits,
    const int*   __restrict__ prev,
    float*       __restrict__ out)
{
    __shared__ unsigned sm_mask[TW];

    const int blk  = blockIdx.x;
    const int row  = blk >> 3;        // SPLIT = 8
    const int tile = blk & 7;
    const int base = tile * TILE;
    const int tid  = threadIdx.x;

    for (int i = tid; i < TW; i += NT) sm_mask[i] = 0u;
    __syncthreads();
    for (int i = tid; i < H_; i += NT) {
        int t = prev[row * H_ + i] - base;
        if ((unsigned)t < (unsigned)TILE)
            atomicOr(&sm_mask[((unsigned)t) >> 5], 1u << (t & 31));
    }
    __syncthreads();

    const float4* __restrict__ l4 = (const float4*)(logits + (size_t)row * V_ + base);
    float4* o4 = (float4*)(out + (size_t)row * V_ + base);
    const float4 z4 = make_float4(0.f, 0.f, 0.f, 0.f);

    for (int i = tid; i < TILE / 4; i += NT) {
        float4 v = __ldcs(&l4[i]);
        int j = i << 2;
        unsigned mw = sm_mask[j >> 5];
        unsigned sh = j & 31;
        float a0 = v.x; if ((mw >> (sh + 0)) & 1u) a0 = (a0 < 0.f) ? a0 * PEN : a0 / PEN; a0 /= TEMP;
        float a1 = v.y; if ((mw >> (sh + 1)) & 1u) a1 = (a1 < 0.f) ? a1 * PEN : a1 / PEN; a1 /= TEMP;
        float a2 = v.z; if ((mw >> (sh + 2)) & 1u) a2 = (a2 < 0.f) ? a2 * PEN : a2 / PEN; a2 /= TEMP;
        float a3 = v.w; if ((mw >> (sh + 3)) & 1u) a3 = (a3 < 0.f) ? a3 * PEN : a3 / PEN; a3 /= TEMP;
        __stcs(&o4[i], z4);
        if (a0 >= T0) { int p = atomicAdd(&g_cnt[row], 1); if (p < CAP) { g_cval[row][p] = a0; g_cidx[row][p] = base + j + 0; } }
        if (a1 >= T0) { int p = atomicAdd(&g_cnt[row], 1); if (p < CAP) { g_cval[row][p] = a1; g_cidx[row][p] = base + j + 1; } }
        if (a2 >= T0) { int p = atomicAdd(&g_cnt[row], 1); if (p < CAP) { g_cval[row][p] = a2; g_cidx[row][p] = base + j + 2; } }
        if (a3 >= T0) { int p = atomicAdd(&g_cnt[row], 1); if (p < CAP) { g_cval[row][p] = a3; g_cidx[row][p] = base + j + 3; } }
    }
}

// ============ K2: per-row selection + nucleus + scatter write ============
__global__ __launch_bounds__(NT) void finalize_kernel(float* __restrict__ out)
{
    __shared__ float cv[CAP];
    __shared__ int   ci[CAP];
    __shared__ short rk[CAP];
    __shared__ float sm_top[TOPSZ];
    __shared__ float sm_e[TOPSZ];
    __shared__ int   sm_m;
    __shared__ float sm_v0, sm_invZ;

    const int row = blockIdx.x;
    const int tid = threadIdx.x;
    const int cnt = g_cnt[row];
    if (cnt < TOPK || cnt > CAP) return;   // fallback kernel owns this row
    const int n = cnt;

    for (int i = tid; i < n; i += NT) { cv[i] = g_cval[row][i]; ci[i] = g_cidx[row][i]; }
    __syncthreads();

    // counting-rank with vocab-index tiebreak (== stable argsort desc)
    for (int i = tid; i < n; i += NT) {
        float v = cv[i];
        int idx = ci[i];
        int r = 0;
        for (int k = 0; k < n; k++) {
            float w = cv[k];
            r += (w > v) || (w == v && ci[k] < idx);
        }
        if (r < TOPSZ) sm_top[r] = v;
        rk[i] = (short)(r < 32767 ? r : 32767);
    }
    __syncthreads();

    if (tid == 0) {
        // JAX top-k keeps ALL values equal to the 50th-largest
        float v50 = sm_top[TOPK - 1];
        int lim = n < TOPSZ ? n : TOPSZ;
        int nk = TOPK;
        while (nk < lim && sm_top[nk] == v50) nk++;

        float v0 = sm_top[0];
        float Z = 0.f;
        for (int i = 0; i < nk; i++) { sm_e[i] = expf(sm_top[i] - v0); Z += sm_e[i]; }
        float cum = 0.f, S = 0.f;
        int m = 0;
        for (int i = 0; i < nk; i++) {
            if (i > 0 && cum > TOPP) break;     // HF shift-right semantics
            cum += sm_e[i] / Z;
            S   += sm_e[i];
            m = i + 1;
        }
        sm_v0 = v0; sm_m = m; sm_invZ = 1.f / S;
    }
    __syncthreads();

    const float v0 = sm_v0, invZ = sm_invZ;
    const int m = sm_m;
    float* orow = out + (size_t)row * V_;
    for (int i = tid; i < n; i += NT) {
        if (rk[i] < m) orow[ci[i]] = expf(cv[i] - v0) * invZ;
    }
}

// ============ K3: exact fallback (runs full two-pass only for deficient rows) ============
__global__ __launch_bounds__(NT) void fallback_kernel(
    const float* __restrict__ logits,
    const int*   __restrict__ prev,
    float*       __restrict__ out)
{
    const int row = blockIdx.x;
    const int cnt = g_cnt[row];
    if (cnt >= TOPK && cnt <= CAP) return;   // common case: nothing to do

    __shared__ unsigned sm_mask[MASKW];
    __shared__ int      sm_hist[NBINS];
    __shared__ float    sm_cval[CAPF];
    __shared__ int      sm_cidx[CAPF];
    __shared__ int      sm_chunk[NT];
    __shared__ float    sm_top[TOPSZ];
    __shared__ float    sm_e[TOPSZ];
    __shared__ int      sm_cnt;
    __shared__ int      sm_bstar;
    __shared__ int      sm_m;
    __shared__ float    sm_v0, sm_invZ;

    const int tid = threadIdx.x;
    const float4* __restrict__ l4 = (const float4*)(logits + (size_t)row * V_);
    float* orow = out + (size_t)row * V_;
    const int NV4 = V_ / 4;

    for (int i = tid; i < MASKW; i += NT) sm_mask[i] = 0u;
    for (int i = tid; i < NBINS; i += NT) sm_hist[i] = 0;
    if (tid == 0) sm_cnt = 0;
    __syncthreads();
    for (int i = tid; i < H_; i += NT) {
        int t = prev[row * H_ + i];
        atomicOr(&sm_mask[((unsigned)t) >> 5], 1u << (t & 31));
    }
    __syncthreads();

    for (int i = tid; i < NV4; i += NT) {
        float4 v = l4[i];
        int j = i << 2;
        unsigned mw = sm_mask[j >> 5];
        unsigned sh = j & 31;
        float a;
        a = v.x; if ((mw >> (sh + 0)) & 1u) a = (a < 0.f) ? a * PEN : a / PEN; a /= TEMP;
        atomicAdd(&sm_hist[ordu(a) >> BSHIFT], 1);
        a = v.y; if ((mw >> (sh + 1)) & 1u) a = (a < 0.f) ? a * PEN : a / PEN; a /= TEMP;
        atomicAdd(&sm_hist[ordu(a) >> BSHIFT], 1);
        a = v.z; if ((mw >> (sh + 2)) & 1u) a = (a < 0.f) ? a * PEN : a / PEN; a /= TEMP;
        atomicAdd(&sm_hist[ordu(a) >> BSHIFT], 1);
        a = v.w; if ((mw >> (sh + 3)) & 1u) a = (a < 0.f) ? a * PEN : a / PEN; a /= TEMP;
        atomicAdd(&sm_hist[ordu(a) >> BSHIFT], 1);
    }
    __syncthreads();

    {
        int s = 0;
        #pragma unroll
        for (int k = 0; k < BPC; k++) s += sm_hist[tid * BPC + k];
        sm_chunk[tid] = s;
        __syncthreads();
        for (int off = 1; off < NT; off <<= 1) {
            int add = (tid + off < NT) ? sm_chunk[tid + off] : 0;
            __syncthreads();
            sm_chunk[tid] += add;
            __syncthreads();
        }
        int myv = sm_chunk[tid];
        int nxt = (tid + 1 < NT) ? sm_chunk[tid + 1] : 0;
        if (myv >= TOPK && nxt < TOPK) {
            int run = nxt;
            int bstar = tid * BPC;
            for (int b = tid * BPC + BPC - 1; b >= tid * BPC; b--) {
                run += sm_hist[b];
                if (run >= TOPK) { bstar = b; break; }
            }
            sm_bstar = bstar;
        }
    }
    __syncthreads();
    const unsigned uth = ((unsigned)sm_bstar) << BSHIFT;

    for (int i = tid; i < NV4; i += NT) {
        float4 v = l4[i];
        int j = i << 2;
        unsigned mw = sm_mask[j >> 5];
        unsigned sh = j & 31;
        float a0 = v.x; if ((mw >> (sh + 0)) & 1u) a0 = (a0 < 0.f) ? a0 * PEN : a0 / PEN; a0 /= TEMP;
        float a1 = v.y; if ((mw >> (sh + 1)) & 1u) a1 = (a1 < 0.f) ? a1 * PEN : a1 / PEN; a1 /= TEMP;
        float a2 = v.z; if ((mw >> (sh + 2)) & 1u) a2 = (a2 < 0.f) ? a2 * PEN : a2 / PEN; a2 /= TEMP;
        float a3 = v.w; if ((mw >> (sh + 3)) & 1u) a3 = (a3 < 0.f) ? a3 * PEN : a3 / PEN; a3 /= TEMP;
        if (ordu(a0) >= uth) { int p = atomicAdd(&sm_cnt, 1); if (p < CAPF) { sm_cval[p] = a0; sm_cidx[p] = j + 0; } }
        if (ordu(a1) >= uth) { int p = atomicAdd(&sm_cnt, 1); if (p < CAPF) { sm_cval[p] = a1; sm_cidx[p] = j + 1; } }
        if (ordu(a2) >= uth) { int p = atomicAdd(&sm_cnt, 1); if (p < CAPF) { sm_cval[p] = a2; sm_cidx[p] = j + 2; } }
        if (ordu(a3) >= uth) { int p = atomicAdd(&sm_cnt, 1); if (p < CAPF) { sm_cval[p] = a3; sm_cidx[p] = j + 3; } }
    }
    __syncthreads();
    const int n = sm_cnt < CAPF ? sm_cnt : CAPF;

    for (int i = tid; i < n; i += NT) {
        float v = sm_cval[i];
        int idx = sm_cidx[i] & IDXMASK;
        int r = 0;
        for (int k = 0; k < n; k++) {
            float w = sm_cval[k];
            r += (w > v) || (w == v && (sm_cidx[k] & IDXMASK) < idx);
        }
        if (r < TOPSZ) sm_top[r] = v;
        int rc = r < 255 ? r : 255;
        sm_cidx[i] = idx | (rc << 17);
    }
    __syncthreads();

    if (tid == 0) {
        float v50 = sm_top[TOPK - 1];
        int lim = n < TOPSZ ? n : TOPSZ;
        int nk = TOPK;
        while (nk < lim && sm_top[nk] == v50) nk++;
        float v0 = sm_top[0];
        float Z = 0.f;
        for (int i = 0; i < nk; i++) { sm_e[i] = expf(sm_top[i] - v0); Z += sm_e[i]; }
        float cum = 0.f, S = 0.f;
        int m = 0;
        for (int i = 0; i < nk; i++) {
            if (i > 0 && cum > TOPP) break;
            cum += sm_e[i] / Z;
            S   += sm_e[i];
            m = i + 1;
        }
        sm_v0 = v0; sm_m = m; sm_invZ = 1.f / S;
    }
    __syncthreads();

    const float v0 = sm_v0, invZ = sm_invZ;
    const int m = sm_m;
    for (int i = tid; i < n; i += NT) {
        int packed = sm_cidx[i];
        int r = packed >> 17;
        if (r < m) orow[packed & IDXMASK] = expf(sm_cval[i] - v0) * invZ;
    }
}

extern "C" void kernel_launch(void* const* d_in, const int* in_sizes, int n_in,
                              void* d_out, int out_size) {
    const float* logits = (const float*)d_in[0];
    const int*   prev   = (const int*)d_in[1];
    float*       out    = (float*)d_out;

    zero_kernel<<<1, B_>>>();
    pass1_kernel<<<B_ * SPLIT, NT>>>(logits, prev, out);
    finalize_kernel<<<B_, NT>>>(out);
    fallback_kernel<<<B_, NT>>>(logits, prev, out);
}